// round 1
// baseline (speedup 1.0000x reference)
#include <cuda_runtime.h>

// HistPredictor: splat B*K 2D Gaussians onto 128x128 grids, normalize per batch.
// B=256, K=16, grid 128x128 over [-2,2]^2, MIN_SIGMA=0.001.
//
// Inputs (metadata order):
//   d_in[0] = mu    [256,16,2] f32
//   d_in[1] = sigma [256,16,2] f32
//   d_in[2] = cov12 [256,16]   f32
//   d_in[3] = pi    [256,16]   f32
// Output: [256,128,128] f32

#define KMIX 16
#define NTHREADS 512

__global__ __launch_bounds__(NTHREADS, 2)
void gmm_hist_kernel(const float* __restrict__ mu,
                     const float* __restrict__ sigma,
                     const float* __restrict__ cov12,
                     const float* __restrict__ pi,
                     float* __restrict__ out)
{
    __shared__ float s_a[KMIX], s_b[KMIX], s_c[KMIX];
    __shared__ float s_mu[KMIX], s_mv[KMIX], s_coef[KMIX];
    __shared__ float s_red[16];

    const int b = blockIdx.x;
    const int t = threadIdx.x;

    // 16 threads compute per-mixture parameters (exactly mirroring reference)
    if (t < KMIX) {
        const int idx = b * KMIX + t;
        float su = fmaxf(sigma[idx * 2 + 0], 0.001f);
        float sv = fmaxf(sigma[idx * 2 + 1], 0.001f);
        float su2 = su * su;
        float sv2 = sv * sv;
        float c11 = su2 + 1e-6f;
        float c22 = sv2 + 1e-6f;
        float off = cov12[idx];
        float det_full = c11 * c22 - off * off;
        // valid = (det_full > 0) & ~isnan(det_full); NaN>0 is false -> covered.
        float ia, ib, ic, det;
        if (det_full > 0.0f) {
            float rdet = 1.0f / det_full;
            ia = c22 * rdet;
            ib = -off * rdet;
            ic = c11 * rdet;
            det = det_full;
        } else {
            ia = 1.0f / su2;
            ib = 0.0f;
            ic = 1.0f / sv2;
            det = su2 * sv2;
        }
        // Fold exp(-0.5*mahal):  e = (-0.5*ia)*du^2 + (-ib)*du*dv + (-0.5*ic)*dv^2
        s_a[t] = -0.5f * ia;
        s_b[t] = -ib;
        s_c[t] = -0.5f * ic;
        s_mu[t] = mu[idx * 2 + 0];
        s_mv[t] = mu[idx * 2 + 1];
        s_coef[t] = pi[idx] / (6.283185307179586f * sqrtf(det + 1e-6f));
    }
    __syncthreads();

    // Grid layout: g = u*128 + v. Thread t owns u = t>>2, v in [(t&3)*32, +32).
    const float H = 4.0f / 127.0f;
    const int u  = t >> 2;
    const int v0 = (t & 3) * 32;
    const float uc    = -2.0f + (float)u  * H;
    const float vbase = -2.0f + (float)v0 * H;

    float acc[32];
#pragma unroll
    for (int j = 0; j < 32; j++) acc[j] = 0.0f;

#pragma unroll 1
    for (int k = 0; k < KMIX; k++) {
        const float du   = uc - s_mu[k];
        const float A    = s_a[k] * du * du;   // -0.5*ia*du^2
        const float Bc   = s_b[k] * du;        // -ib*du
        const float ic2  = s_c[k];             // -0.5*ic
        const float mv   = s_mv[k];
        const float coef = s_coef[k];
#pragma unroll
        for (int j = 0; j < 32; j++) {
            float dv = (vbase - mv) + (float)j * H;
            float e  = fmaf(dv, fmaf(ic2, dv, Bc), A);  // <= 0 always (PSD)
            acc[j]   = fmaf(coef, __expf(e), acc[j]);
        }
    }

    // Per-batch sum for normalization
    float s = 0.0f;
#pragma unroll
    for (int j = 0; j < 32; j++) s += acc[j];
#pragma unroll
    for (int o = 16; o > 0; o >>= 1) s += __shfl_xor_sync(0xffffffffu, s, o);

    const int warp = t >> 5;
    const int lane = t & 31;
    if (lane == 0) s_red[warp] = s;
    __syncthreads();
    if (warp == 0) {
        float x = (lane < 16) ? s_red[lane] : 0.0f;
#pragma unroll
        for (int o = 8; o > 0; o >>= 1) x += __shfl_xor_sync(0xffffffffu, x, o);
        if (lane == 0) s_red[0] = (x > 0.0f) ? (1.0f / x) : 1.0f;
    }
    __syncthreads();
    const float inv = s_red[0];

    float* op = out + (size_t)b * 16384 + (size_t)u * 128 + v0;
#pragma unroll
    for (int j = 0; j < 32; j += 4) {
        float4 w = make_float4(acc[j] * inv, acc[j + 1] * inv,
                               acc[j + 2] * inv, acc[j + 3] * inv);
        *reinterpret_cast<float4*>(op + j) = w;
    }
}

extern "C" void kernel_launch(void* const* d_in, const int* in_sizes, int n_in,
                              void* d_out, int out_size)
{
    const float* mu    = (const float*)d_in[0];
    const float* sigma = (const float*)d_in[1];
    const float* cov12 = (const float*)d_in[2];
    const float* pi    = (const float*)d_in[3];
    float* out = (float*)d_out;
    gmm_hist_kernel<<<256, NTHREADS>>>(mu, sigma, cov12, pi, out);
}

// round 2
// speedup vs baseline: 1.2112x; 1.2112x over previous
#include <cuda_runtime.h>

// HistPredictor: splat B*K 2D Gaussians onto 128x128 grids, normalize per batch.
// B=256, K=16, grid 128x128 over [-2,2]^2, MIN_SIGMA=0.001.
//
// R2: exponent evaluated directly in log2 domain as quadratic-in-j
//     (2 FFMA-imm + ex2.approx + 1 FFMA per point), warp-uniform mixture skip.

#define KMIX 16
#define NTHREADS 512

__device__ __forceinline__ float ex2f(float x) {
    float r;
    asm("ex2.approx.f32 %0, %1;" : "=f"(r) : "f"(x));
    return r;
}

__global__ __launch_bounds__(NTHREADS, 2)
void gmm_hist_kernel(const float* __restrict__ mu,
                     const float* __restrict__ sigma,
                     const float* __restrict__ cov12,
                     const float* __restrict__ pi,
                     float* __restrict__ out)
{
    // coefficients pre-scaled by log2(e): e2 = a2*du^2 + b2*du*dv + c2*dv^2
    __shared__ float s_a[KMIX], s_b[KMIX], s_c[KMIX], s_c2[KMIX];
    __shared__ float s_mu[KMIX], s_mv[KMIX], s_coef[KMIX];
    __shared__ float s_R[KMIX], s_S[KMIX];
    __shared__ float s_red[16];

    const int b = blockIdx.x;
    const int t = threadIdx.x;

    const float H  = 4.0f / 127.0f;
    const float L2E = 1.4426950408889634f;

    if (t < KMIX) {
        const int idx = b * KMIX + t;
        float su = fmaxf(sigma[idx * 2 + 0], 0.001f);
        float sv = fmaxf(sigma[idx * 2 + 1], 0.001f);
        float su2 = su * su;
        float sv2 = sv * sv;
        float c11 = su2 + 1e-6f;
        float c22 = sv2 + 1e-6f;
        float off = cov12[idx];
        float det_full = c11 * c22 - off * off;
        // valid = (det_full > 0) & ~isnan(det_full); NaN>0 is false -> covered.
        float ia, ib, ic, det;
        if (det_full > 0.0f) {
            float rdet = 1.0f / det_full;
            ia = c22 * rdet;
            ib = -off * rdet;
            ic = c11 * rdet;
            det = det_full;
        } else {
            ia = 1.0f / su2;
            ib = 0.0f;
            ic = 1.0f / sv2;
            det = su2 * sv2;
        }
        float a2 = -0.5f * L2E * ia;   // coef of du^2   (log2 domain)
        float b2 = -L2E * ib;          // coef of du*dv
        float c2 = -0.5f * L2E * ic;   // coef of dv^2   (always < 0)
        s_a[t]  = a2;
        s_b[t]  = b2;
        s_c[t]  = c2;
        s_c2[t] = 2.0f * c2;
        float R = c2 * (H * H);        // warp-uniform per k, strictly < 0
        s_R[t]  = R;
        s_S[t]  = -0.5f / R;           // for vertex j* = Q * S
        s_mu[t] = mu[idx * 2 + 0];
        s_mv[t] = mu[idx * 2 + 1];
        s_coef[t] = pi[idx] / (6.283185307179586f * sqrtf(det + 1e-6f));
    }
    __syncthreads();

    // Grid layout: g = u*128 + v. Thread t owns u = t>>2, v in [(t&3)*32, +32).
    const int u  = t >> 2;
    const int v0 = (t & 3) * 32;
    const float uc    = -2.0f + (float)u  * H;
    const float vbase = -2.0f + (float)v0 * H;

    float acc[32];
#pragma unroll
    for (int j = 0; j < 32; j++) acc[j] = 0.0f;

#pragma unroll 1
    for (int k = 0; k < KMIX; k++) {
        const float du  = uc    - s_mu[k];
        const float dv0 = vbase - s_mv[k];
        // e2(j) = P + Q*j + R*j^2  with dv = dv0 + j*H
        const float R = s_R[k];
        const float Q = fmaf(s_c2[k], dv0, s_b[k] * du) * H;
        const float P = fmaf(fmaf(s_b[k], dv0, s_a[k] * du), du, (s_c[k] * dv0) * dv0);
        const float coef = s_coef[k];

        // warp-uniform skip: max of concave e2 over j in [0,31]
        float jc = fminf(fmaxf(Q * s_S[k], 0.0f), 31.0f);
        float ev = fmaf(jc, fmaf(R, jc, Q), P);
        if (__ballot_sync(0xffffffffu, ev >= -30.0f) == 0u) continue;

#pragma unroll
        for (int j = 0; j < 32; j++) {
            const float jf = (float)j;
            float e = fmaf(jf, fmaf(R, jf, Q), P);   // 2 FFMA (imm multiplier)
            acc[j]  = fmaf(coef, ex2f(e), acc[j]);   // MUFU.EX2 + FFMA
        }
    }

    // Per-batch sum for normalization
    float s = 0.0f;
#pragma unroll
    for (int j = 0; j < 32; j++) s += acc[j];
#pragma unroll
    for (int o = 16; o > 0; o >>= 1) s += __shfl_xor_sync(0xffffffffu, s, o);

    const int warp = t >> 5;
    const int lane = t & 31;
    if (lane == 0) s_red[warp] = s;
    __syncthreads();
    if (warp == 0) {
        float x = (lane < 16) ? s_red[lane] : 0.0f;
#pragma unroll
        for (int o = 8; o > 0; o >>= 1) x += __shfl_xor_sync(0xffffffffu, x, o);
        if (lane == 0) s_red[0] = (x > 0.0f) ? (1.0f / x) : 1.0f;
    }
    __syncthreads();
    const float inv = s_red[0];

    float* op = out + (size_t)b * 16384 + (size_t)u * 128 + v0;
#pragma unroll
    for (int j = 0; j < 32; j += 4) {
        float4 w = make_float4(acc[j] * inv, acc[j + 1] * inv,
                               acc[j + 2] * inv, acc[j + 3] * inv);
        *reinterpret_cast<float4*>(op + j) = w;
    }
}

extern "C" void kernel_launch(void* const* d_in, const int* in_sizes, int n_in,
                              void* d_out, int out_size)
{
    const float* mu    = (const float*)d_in[0];
    const float* sigma = (const float*)d_in[1];
    const float* cov12 = (const float*)d_in[2];
    const float* pi    = (const float*)d_in[3];
    float* out = (float*)d_out;
    gmm_hist_kernel<<<256, NTHREADS>>>(mu, sigma, cov12, pi, out);
}